// round 15
// baseline (speedup 1.0000x reference)
#include <cuda_runtime.h>
#include <cuda_fp16.h>
#include <math.h>
#include <stdint.h>

// Problem constants
#define BB   2
#define SS   2048
#define DD   768
#define HH   12
#define HDIM 64
#define QKVD 2304           // 3*D per token
#define NTOK (BB*SS)        // 4096

// Scratch (allocation-free rule: __device__ globals)
__device__ __half g_qkvH[(size_t)NTOK * QKVD];  // roped Q(scaled),K + V, fp16 row-major
__device__ float  g_rope[(size_t)NTOK * 64];    // [token][cos32|sin32]
__device__ __half g_hidH[(size_t)NTOK * DD];    // hidden as A-image (fp16)
__device__ __half g_attnH[(size_t)NTOK * DD];   // attn out as A-image (fp16)
__device__ __half g_wqH[(size_t)QKVD * DD];     // Wqkv as B-image (fp16)
__device__ __half g_woH[(size_t)DD * DD];       // Wo as B-image (fp16)
__device__ float  g_part[(size_t)3 * NTOK * DD]; // Wo split-K partials

__device__ __forceinline__ uint32_t smem_u32(const void* p) {
    uint32_t a;
    asm("{ .reg .u64 t; cvta.to.shared.u64 t, %1; cvt.u32.u64 %0, t; }"
        : "=r"(a) : "l"(p));
    return a;
}

__device__ __forceinline__ void mma_f16(float c[4], const uint32_t a[4], const uint32_t b[2]) {
    asm volatile(
        "mma.sync.aligned.m16n8k16.row.col.f32.f16.f16.f32 "
        "{%0,%1,%2,%3}, {%4,%5,%6,%7}, {%8,%9}, {%0,%1,%2,%3};"
        : "+f"(c[0]), "+f"(c[1]), "+f"(c[2]), "+f"(c[3])
        : "r"(a[0]), "r"(a[1]), "r"(a[2]), "r"(a[3]), "r"(b[0]), "r"(b[1]));
}

#define LDSM_X4(r0,r1,r2,r3,a) \
    asm volatile("ldmatrix.sync.aligned.m8n8.x4.shared.b16 {%0,%1,%2,%3}, [%4];" \
                 : "=r"(r0), "=r"(r1), "=r"(r2), "=r"(r3) : "r"(a))
#define LDSM_X4T(r0,r1,r2,r3,a) \
    asm volatile("ldmatrix.sync.aligned.m8n8.x4.trans.shared.b16 {%0,%1,%2,%3}, [%4];" \
                 : "=r"(r0), "=r"(r1), "=r"(r2), "=r"(r3) : "r"(a))

#define CP_ASYNC16(dst, src) \
    asm volatile("cp.async.cg.shared.global [%0], [%1], 16;" :: "r"(dst), "l"(src))
#define CP_COMMIT() asm volatile("cp.async.commit_group;" ::: "memory")
#define CP_WAIT4()  asm volatile("cp.async.wait_group 4;"  ::: "memory")

// ---------------------------------------------------------------------------
// fp16 tile-image local offsets (within one 128x32 tile = 4096 halves).
// ---------------------------------------------------------------------------
__device__ __forceinline__ int aimg_local(int r, int k) {
    const int mi = (r >> 4) & 7, rr = r & 15;
    const int ki = (k >> 4) & 1, kk = k & 15;
    const int lane = ((rr & 7) << 2) + ((kk & 7) >> 1);
    const int e = (kk & 1) + ((rr >> 3) << 1) + ((kk >> 3) << 2);
    return (((mi << 1) + ki) << 8) + (lane << 3) + e;
}
__device__ __forceinline__ int bimg_local(int n, int k) {
    const int pr = (n >> 4) & 7, p = (n >> 3) & 1, nn = n & 7;
    const int ki = (k >> 4) & 1, kk = k & 15;
    const int lane = (nn << 2) + ((kk & 7) >> 1);
    const int e = (kk & 1) + ((kk >> 3) << 1) + (p << 2);
    return (((pr << 1) + ki) << 8) + (lane << 3) + e;
}

// ---------------------------------------------------------------------------
// Fused prologue: RoPE table + smem-staged tile-image transforms.
// Blocks: [0,512) rope; [512,1280) hidden-A (768 tiles);
//         [1280,1712) Wqkv-B (432 tiles); [1712,1856) Wo-B (144 tiles).
// ---------------------------------------------------------------------------
__global__ void prologue(const float* __restrict__ hidden,
                         const float* __restrict__ wqkv,
                         const float* __restrict__ wo,
                         const int*   __restrict__ pos_ids)
{
    const int bid = blockIdx.x;
    const int t   = threadIdx.x;
    if (bid < 512) {
        const int idx = bid * 256 + t;                    // NTOK*32
        const int bs = idx >> 5;
        const int d  = idx & 31;
        const float FCOEF = -0.41524101186091903f;
        const float pos = (float)pos_ids[bs];
        const float f = pos * exp2f((float)d * FCOEF);
        float sn, cs;
        sincosf(f, &sn, &cs);
        g_rope[(size_t)bs * 64 + d]      = cs;
        g_rope[(size_t)bs * 64 + 32 + d] = sn;
        return;
    }

    __shared__ __half img[4096];
    const float* src;
    __half* dst;
    bool isA;
    if (bid < 1280) {
        const int tile = bid - 512;
        const int mt = tile / 24, kc = tile % 24;
        src = hidden + (size_t)mt * 128 * DD + kc * 32;
        dst = g_hidH + ((size_t)(mt * 24 + kc) << 12);
        isA = true;
    } else if (bid < 1712) {
        const int tile = bid - 1280;
        const int nt = tile / 24, kc = tile % 24;
        src = wqkv + (size_t)nt * 128 * DD + kc * 32;
        dst = g_wqH + ((size_t)(nt * 24 + kc) << 12);
        isA = false;
    } else {
        const int tile = bid - 1712;
        const int nt = tile / 24, kc = tile % 24;
        src = wo + (size_t)nt * 128 * DD + kc * 32;
        dst = g_woH + ((size_t)(nt * 24 + kc) << 12);
        isA = false;
    }

#pragma unroll
    for (int i = 0; i < 4; i++) {
        const int q = t + 256 * i;       // 0..1023
        const int r = q >> 3;            // row 0..127
        const int k = (q & 7) << 2;      // 0,4,..,28
        const float4 v = *(const float4*)(src + (size_t)r * DD + k);
        const int o0 = isA ? aimg_local(r, k)     : bimg_local(r, k);
        const int o1 = isA ? aimg_local(r, k + 2) : bimg_local(r, k + 2);
        *(__half2*)(img + o0) = __floats2half2_rn(v.x, v.y);
        *(__half2*)(img + o1) = __floats2half2_rn(v.z, v.w);
    }
    __syncthreads();
#pragma unroll
    for (int i = 0; i < 2; i++)
        ((uint4*)dst)[t + 256 * i] = ((const uint4*)img)[t + 256 * i];
}

// ---------------------------------------------------------------------------
// QKV GEMM with fused RoPE epilogue -> fp16 g_qkvH (unchanged from round 14).
// ---------------------------------------------------------------------------
#define GEMM_SMEM 98304   // 6 buffers x (8KB A + 8KB B)

__global__ __launch_bounds__(256, 2) void gemm_qkv(const __half* __restrict__ Aimg,
                                                   const __half* __restrict__ Bimg,
                                                   int ntileK)
{
    extern __shared__ __half smh[];
    const uint32_t sbase = smem_u32(smh);
    const int tid    = threadIdx.x;
    const int wid    = tid >> 5;
    const int lane   = tid & 31;
    const int mt     = blockIdx.y;
    const int nt     = blockIdx.x;
    const int warp_m = wid >> 1;   // 0..3
    const int warp_n = wid & 1;    // 0..1

    float acc[2][8][4];
#pragma unroll
    for (int a = 0; a < 2; a++)
#pragma unroll
        for (int b = 0; b < 8; b++)
#pragma unroll
            for (int r = 0; r < 4; r++) acc[a][b][r] = 0.f;

    const int nch = ntileK;
    const __half* Atile0 = Aimg + ((size_t)(mt * ntileK) << 12) + (tid << 3);
    const __half* Btile0 = Bimg + ((size_t)(nt * ntileK) << 12) + (tid << 3);

#define ISSUE(c) do {                                                     \
    if ((c) < nch) {                                                      \
        const __half* As_ = Atile0 + ((size_t)(c) << 12);                 \
        const __half* Bs_ = Btile0 + ((size_t)(c) << 12);                 \
        uint32_t sa_ = sbase + ((c) % 6) * 16384u + (tid << 4);           \
        CP_ASYNC16(sa_,          As_);                                    \
        CP_ASYNC16(sa_ + 4096u,  As_ + 2048);                             \
        CP_ASYNC16(sa_ + 8192u,  Bs_);                                    \
        CP_ASYNC16(sa_ + 12288u, Bs_ + 2048);                             \
    }                                                                     \
    CP_COMMIT();                                                          \
} while (0)

    ISSUE(0); ISSUE(1); ISSUE(2); ISSUE(3); ISSUE(4);

    const int afo = warp_m * 1024 + lane * 8;
    const int bfo = 4096 + warp_n * 2048 + lane * 8;

    for (int c = 0; c < nch; c++) {
        CP_WAIT4();
        __syncthreads();

        const __half* s = smh + (c % 6) * 8192;
#pragma unroll
        for (int ki = 0; ki < 2; ki++) {
            uint32_t af[2][4], bf[8][2];
#pragma unroll
            for (int a = 0; a < 2; a++) {
                uint4 v = *(const uint4*)(s + afo + a * 512 + ki * 256);
                af[a][0] = v.x; af[a][1] = v.y; af[a][2] = v.z; af[a][3] = v.w;
            }
#pragma unroll
            for (int t2 = 0; t2 < 4; t2++) {
                uint4 v = *(const uint4*)(s + bfo + t2 * 512 + ki * 256);
                bf[2*t2][0]   = v.x; bf[2*t2][1]   = v.y;
                bf[2*t2+1][0] = v.z; bf[2*t2+1][1] = v.w;
            }
#pragma unroll
            for (int a = 0; a < 2; a++)
#pragma unroll
                for (int b = 0; b < 8; b++)
                    mma_f16(acc[a][b], af[a], bf[b]);
        }
        ISSUE(c + 5);
    }

    const int g = lane >> 2, u = lane & 3;
    const int colb = nt * 128 + warp_n * 64;
    const int region = colb / DD;                // 0=Q, 1=K, 2=V
    const float SC = (region == 0) ? 0.18033688011112042f : 1.0f;

#pragma unroll
    for (int a = 0; a < 2; a++) {
        const int tok0 = mt * 128 + warp_m * 32 + a * 16 + g;
        const int tok1 = tok0 + 8;
        __half* o0 = g_qkvH + (size_t)tok0 * QKVD + colb;
        __half* o1 = g_qkvH + (size_t)tok1 * QKVD + colb;
        if (region == 2) {
#pragma unroll
            for (int b = 0; b < 8; b++) {
                const int cc = 8 * b + 2 * u;
                *(__half2*)(o0 + cc) = __floats2half2_rn(acc[a][b][0], acc[a][b][1]);
                *(__half2*)(o1 + cc) = __floats2half2_rn(acc[a][b][2], acc[a][b][3]);
            }
        } else {
            const float* rp0 = g_rope + (size_t)tok0 * 64;
            const float* rp1 = g_rope + (size_t)tok1 * 64;
#pragma unroll
            for (int b = 0; b < 4; b++) {
                const int d = 8 * b + 2 * u;
                const float x0 = acc[a][b][0],   x1 = acc[a][b][1];
                const float y0 = acc[a][b+4][0], y1 = acc[a][b+4][1];
                const float c0 = rp0[d], c1 = rp0[d+1], s0 = rp0[32+d], s1 = rp0[32+d+1];
                *(__half2*)(o0 + d)      = __floats2half2_rn((x0*c0 - y0*s0)*SC, (x1*c1 - y1*s1)*SC);
                *(__half2*)(o0 + 32 + d) = __floats2half2_rn((y0*c0 + x0*s0)*SC, (y1*c1 + x1*s1)*SC);
                const float x2 = acc[a][b][2],   x3 = acc[a][b][3];
                const float y2 = acc[a][b+4][2], y3 = acc[a][b+4][3];
                const float c2 = rp1[d], c3 = rp1[d+1], s2 = rp1[32+d], s3 = rp1[32+d+1];
                *(__half2*)(o1 + d)      = __floats2half2_rn((x2*c2 - y2*s2)*SC, (x3*c3 - y3*s3)*SC);
                *(__half2*)(o1 + 32 + d) = __floats2half2_rn((y2*c2 + x2*s2)*SC, (y3*c3 + x3*s3)*SC);
            }
        }
    }
#undef ISSUE
}

// ---------------------------------------------------------------------------
// Wo GEMM, split-K x3: grid (6, 32, 3); split s handles chunks [8s, 8s+8).
// Partials -> g_part[s]; reduce3 sums them into d_out.
// ---------------------------------------------------------------------------
__global__ __launch_bounds__(256, 2) void gemm_wo(const __half* __restrict__ Aimg,
                                                  const __half* __restrict__ Bimg,
                                                  float* __restrict__ Cpart,
                                                  int N, int ntileK_total)
{
    extern __shared__ __half smh[];
    const uint32_t sbase = smem_u32(smh);
    const int tid    = threadIdx.x;
    const int wid    = tid >> 5;
    const int lane   = tid & 31;
    const int mt     = blockIdx.y;
    const int nt     = blockIdx.x;
    const int sp     = blockIdx.z;       // split 0..2
    const int koff   = sp * 8;
    const int nch    = 8;
    const int warp_m = wid >> 2;
    const int warp_n = wid & 3;

    float* C = Cpart + (size_t)sp * NTOK * DD;

    float acc[4][4][4];
#pragma unroll
    for (int a = 0; a < 4; a++)
#pragma unroll
        for (int b = 0; b < 4; b++)
#pragma unroll
            for (int r = 0; r < 4; r++) acc[a][b][r] = 0.f;

    const __half* Atile0 = Aimg + ((size_t)(mt * ntileK_total + koff) << 12) + (tid << 3);
    const __half* Btile0 = Bimg + ((size_t)(nt * ntileK_total + koff) << 12) + (tid << 3);

#define ISSUE(c) do {                                                     \
    if ((c) < nch) {                                                      \
        const __half* As_ = Atile0 + ((size_t)(c) << 12);                 \
        const __half* Bs_ = Btile0 + ((size_t)(c) << 12);                 \
        uint32_t sa_ = sbase + ((c) % 6) * 16384u + (tid << 4);           \
        CP_ASYNC16(sa_,          As_);                                    \
        CP_ASYNC16(sa_ + 4096u,  As_ + 2048);                             \
        CP_ASYNC16(sa_ + 8192u,  Bs_);                                    \
        CP_ASYNC16(sa_ + 12288u, Bs_ + 2048);                             \
    }                                                                     \
    CP_COMMIT();                                                          \
} while (0)

    ISSUE(0); ISSUE(1); ISSUE(2); ISSUE(3); ISSUE(4);

    const int afo = warp_m * 2048 + lane * 8;
    const int bfo = 4096 + warp_n * 1024 + lane * 8;

    for (int c = 0; c < nch; c++) {
        CP_WAIT4();
        __syncthreads();

        const __half* s = smh + (c % 6) * 8192;
#pragma unroll
        for (int ki = 0; ki < 2; ki++) {
            uint32_t af[4][4], bf[4][2];
#pragma unroll
            for (int a = 0; a < 4; a++) {
                uint4 v = *(const uint4*)(s + afo + a * 512 + ki * 256);
                af[a][0] = v.x; af[a][1] = v.y; af[a][2] = v.z; af[a][3] = v.w;
            }
#pragma unroll
            for (int t2 = 0; t2 < 2; t2++) {
                uint4 v = *(const uint4*)(s + bfo + t2 * 512 + ki * 256);
                bf[2*t2][0]   = v.x; bf[2*t2][1]   = v.y;
                bf[2*t2+1][0] = v.z; bf[2*t2+1][1] = v.w;
            }
#pragma unroll
            for (int a = 0; a < 4; a++)
#pragma unroll
                for (int b = 0; b < 4; b++)
                    mma_f16(acc[a][b], af[a], bf[b]);
        }
        ISSUE(c + 5);
    }

    const int g = lane >> 2, u = lane & 3;
#pragma unroll
    for (int a = 0; a < 4; a++) {
        const int row = mt * 128 + warp_m * 64 + a * 16 + g;
#pragma unroll
        for (int b = 0; b < 4; b++) {
            const int col = nt * 128 + warp_n * 32 + b * 8 + 2 * u;
            *(float2*)(C + (size_t)row * N + col)       = make_float2(acc[a][b][0], acc[a][b][1]);
            *(float2*)(C + (size_t)(row + 8) * N + col) = make_float2(acc[a][b][2], acc[a][b][3]);
        }
    }
#undef ISSUE
}

__global__ void reduce3(float* __restrict__ out)
{
    const int i = blockIdx.x * 256 + threadIdx.x;   // over NTOK*DD/4
    const float4* p0 = (const float4*)g_part;
    const float4* p1 = (const float4*)(g_part + (size_t)NTOK * DD);
    const float4* p2 = (const float4*)(g_part + (size_t)2 * NTOK * DD);
    float4 a = p0[i], b = p1[i], c = p2[i];
    a.x += b.x + c.x;
    a.y += b.y + c.y;
    a.z += b.z + c.z;
    a.w += b.w + c.w;
    ((float4*)out)[i] = a;
}

// ---------------------------------------------------------------------------
// Sliding-window attention (unchanged from round 14).
// ---------------------------------------------------------------------------
#define KPH 72
#define VHP 72
#define QPH 72
#define VH_OFF (256 * KPH)
#define QH_OFF (VH_OFF + 256 * VHP)
#define ATTN_SMEM ((QH_OFF + 128 * QPH) * 2)   // 92160 bytes

__global__ __launch_bounds__(256, 2) void attn_mma()
{
    extern __shared__ __half smha[];
    __half* Kh = smha;
    __half* Vh = smha + VH_OFF;
    __half* Qh = smha + QH_OFF;

    const int tid  = threadIdx.x;
    const int lane = tid & 31;
    const int w    = tid >> 5;
    const int g    = lane >> 2;
    const int t    = lane & 3;
    const int j    = lane >> 3;
    const int rim  = lane & 7;
    const int qb   = blockIdx.x;
    const int bh   = blockIdx.y;
    const int b    = bh / HH;
    const int h    = bh % HH;
    const int kstart = qb * 128 - 64;

    // ---- Phase A: pure coalesced copy ----
    {
        const int rg8 = tid >> 3;
        const int c8  = tid & 7;
#pragma unroll
        for (int i = 0; i < 8; i++) {
            const int r  = rg8 + 32 * i;
            const int kg = kstart + r;
            uint4* kd = (uint4*)(Kh + r * KPH + c8 * 8);
            uint4* vd = (uint4*)(Vh + r * VHP + c8 * 8);
            if (kg >= 0 && kg < SS) {
                const __half* src = g_qkvH + ((size_t)(b * SS + kg)) * QKVD + h * HDIM + c8 * 8;
                *kd = *(const uint4*)(src + DD);
                *vd = *(const uint4*)(src + 2 * DD);
            } else {
                const uint4 z = make_uint4(0, 0, 0, 0);
                *kd = z;
                *vd = z;
            }
        }
#pragma unroll
        for (int i = 0; i < 4; i++) {
            const int r  = rg8 + 32 * i;
            const int qg = qb * 128 + r;
            *(uint4*)(Qh + r * QPH + c8 * 8) =
                *(const uint4*)(g_qkvH + ((size_t)(b * SS + qg)) * QKVD + h * HDIM + c8 * 8);
        }
    }
    __syncthreads();

    const uint32_t kh_base = smem_u32(Kh);
    const uint32_t vh_base = smem_u32(Vh);
    const uint32_t qh_base = smem_u32(Qh);
    const uint32_t pw_base = qh_base + (uint32_t)((w << 4) * QPH * 2);

    const int rl = (w << 4) + g;
    uint32_t aq[4][4];
    {
        const uint32_t qa = qh_base +
            (uint32_t)((((w << 4) + rim + 8 * (j & 1)) * QPH + 8 * (j >> 1)) * 2);
#pragma unroll
        for (int s = 0; s < 4; s++)
            LDSM_X4(aq[s][0], aq[s][1], aq[s][2], aq[s][3], qa + 32u * s);
    }
    __syncwarp();

    float m0 = -1e4f, m1 = -1e4f, l0 = 0.f, l1 = 0.f;
    float oacc[8][4];
#pragma unroll
    for (int d = 0; d < 8; d++)
#pragma unroll
        for (int r = 0; r < 4; r++) oacc[d][r] = 0.f;

    __half* Pw = Qh + (w << 4) * QPH;
    const int cw = (w >= 4) ? 1 : 0;

    const uint32_t k_lds0 = kh_base + (uint32_t)(((8 * (j >> 1) + rim) * KPH + 8 * (j & 1)) * 2);
    const uint32_t v_lds0 = vh_base + (uint32_t)(((8 * (j & 1) + rim) * VHP + 8 * (j >> 1)) * 2);
    const uint32_t p_lds0 = pw_base + (uint32_t)(((rim + 8 * (j & 1)) * QPH + 8 * (j >> 1)) * 2);

    for (int ci = 0; ci < 3; ci++) {
        const int kbase = (cw + ci) * 64;

        float sacc[8][4];
#pragma unroll
        for (int q = 0; q < 8; q++)
#pragma unroll
            for (int r = 0; r < 4; r++) sacc[q][r] = 0.f;

#pragma unroll
        for (int s = 0; s < 4; s++) {
#pragma unroll
            for (int jp = 0; jp < 4; jp++) {
                uint32_t r0, r1, r2, r3;
                const uint32_t ka = k_lds0 +
                    (uint32_t)((kbase + 16 * jp) * KPH * 2) + 32u * s;
                LDSM_X4(r0, r1, r2, r3, ka);
                uint32_t b0[2] = {r0, r1};
                uint32_t b1[2] = {r2, r3};
                mma_f16(sacc[2 * jp],     aq[s], b0);
                mma_f16(sacc[2 * jp + 1], aq[s], b1);
            }
        }

        float mx0 = -30000.f, mx1 = -30000.f;
#pragma unroll
        for (int jt = 0; jt < 8; jt++) {
            const int k0 = kbase + 8 * jt + 2 * t;
            const int k1 = k0 + 1;
            const int kg0 = kstart + k0, kg1 = kstart + k1;
            const bool in0 = (kg0 >= 0) & (kg0 < SS);
            const bool in1 = (kg1 >= 0) & (kg1 < SS);
            const bool v00 = in0 && ((unsigned)(k0 - rl) <= 128u);
            const bool v01 = in1 && ((unsigned)(k1 - rl) <= 128u);
            const bool v10 = in0 && ((unsigned)(k0 - rl - 8) <= 128u);
            const bool v11 = in1 && ((unsigned)(k1 - rl - 8) <= 128u);
            sacc[jt][0] = v00 ? sacc[jt][0] : -30000.f;
            sacc[jt][1] = v01 ? sacc[jt][1] : -30000.f;
            sacc[jt][2] = v10 ? sacc[jt][2] : -30000.f;
            sacc[jt][3] = v11 ? sacc[jt][3] : -30000.f;
            mx0 = fmaxf(mx0, fmaxf(sacc[jt][0], sacc[jt][1]));
            mx1 = fmaxf(mx1, fmaxf(sacc[jt][2], sacc[jt][3]));
        }
        mx0 = fmaxf(mx0, __shfl_xor_sync(0xffffffff, mx0, 1));
        mx0 = fmaxf(mx0, __shfl_xor_sync(0xffffffff, mx0, 2));
        mx1 = fmaxf(mx1, __shfl_xor_sync(0xffffffff, mx1, 1));
        mx1 = fmaxf(mx1, __shfl_xor_sync(0xffffffff, mx1, 2));

        const float m0n = fmaxf(m0, mx0);
        const float m1n = fmaxf(m1, mx1);
        const float a0 = exp2f(m0 - m0n);
        const float a1 = exp2f(m1 - m1n);
        m0 = m0n; m1 = m1n;
        l0 *= a0; l1 *= a1;
#pragma unroll
        for (int d = 0; d < 8; d++) {
            oacc[d][0] *= a0; oacc[d][1] *= a0;
            oacc[d][2] *= a1; oacc[d][3] *= a1;
        }

        float rs0 = 0.f, rs1 = 0.f;
#pragma unroll
        for (int jt = 0; jt < 8; jt++) {
            __half2 hp0 = __floats2half2_rn(exp2f(sacc[jt][0] - m0),
                                            exp2f(sacc[jt][1] - m0));
            __half2 hp1 = __floats2half2_rn(exp2f(sacc[jt][2] - m1),
                                            exp2f(sacc[jt][3] - m1));
            float2 f0 = __half22float2(hp0);
            float2 f1 = __half22float2(hp1);
            rs0 += f0.x + f0.y;
            rs1 += f1.x + f1.y;
            const int pc = 8 * jt + 2 * t;
            *(__half2*)(Pw + g * QPH + pc)       = hp0;
            *(__half2*)(Pw + (g + 8) * QPH + pc) = hp1;
        }
        rs0 += __shfl_xor_sync(0xffffffff, rs0, 1);
        rs0 += __shfl_xor_sync(0xffffffff, rs0, 2);
        rs1 += __shfl_xor_sync(0xffffffff, rs1, 1);
        rs1 += __shfl_xor_sync(0xffffffff, rs1, 2);
        l0 += rs0; l1 += rs1;
        __syncwarp();

#pragma unroll
        for (int s = 0; s < 4; s++) {
            uint32_t pa[4];
            LDSM_X4(pa[0], pa[1], pa[2], pa[3], p_lds0 + 32u * s);
#pragma unroll
            for (int dp = 0; dp < 4; dp++) {
                uint32_t r0, r1, r2, r3;
                const uint32_t va = v_lds0 +
                    (uint32_t)((kbase + 16 * s) * VHP * 2) + 32u * dp;
                LDSM_X4T(r0, r1, r2, r3, va);
                uint32_t b0[2] = {r0, r1};
                uint32_t b1[2] = {r2, r3};
                mma_f16(oacc[2 * dp],     pa, b0);
                mma_f16(oacc[2 * dp + 1], pa, b1);
            }
        }
        __syncwarp();
    }

    __syncthreads();
    __half* stage = Kh;
    const float inv0 = 1.f / l0;
    const float inv1 = 1.f / l1;
#pragma unroll
    for (int u = 0; u < 4; u++) {
        __half2 e01 = __floats2half2_rn(oacc[2*u][0]   * inv0, oacc[2*u][1]   * inv0);
        __half2 e23 = __floats2half2_rn(oacc[2*u][2]   * inv1, oacc[2*u][3]   * inv1);
        __half2 e45 = __floats2half2_rn(oacc[2*u+1][0] * inv0, oacc[2*u+1][1] * inv0);
        __half2 e67 = __floats2half2_rn(oacc[2*u+1][2] * inv1, oacc[2*u+1][3] * inv1);
        uint4 pack;
        pack.x = *(uint32_t*)&e01;
        pack.y = *(uint32_t*)&e23;
        pack.z = *(uint32_t*)&e45;
        pack.w = *(uint32_t*)&e67;
        __half* dst = stage + ((u >> 1) << 12) + (((w << 1) + (u & 1)) << 8) + (lane << 3);
        *(uint4*)dst = pack;
    }
    __syncthreads();

    {
        const int mt = (b * SS + qb * 128) >> 7;
        const int kc0 = h * 2;
        __half* gdst = g_attnH + ((size_t)(mt * (DD / 32) + kc0) << 12);
        const uint4* src = (const uint4*)stage;
        uint4* dst = (uint4*)gdst;
#pragma unroll
        for (int i = 0; i < 4; i++)
            dst[tid + 256 * i] = src[tid + 256 * i];
    }
}

// ---------------------------------------------------------------------------
extern "C" void kernel_launch(void* const* d_in, const int* in_sizes, int n_in,
                              void* d_out, int out_size)
{
    const float* hidden = (const float*)d_in[0];
    const float* wqkv   = (const float*)d_in[1];
    const float* wo     = (const float*)d_in[2];
    const int*   pos    = (const int*)d_in[4];
    float*       out    = (float*)d_out;

    __half *hidH_p, *attnH_p, *wqH_p, *woH_p;
    float  *part_p;
    cudaGetSymbolAddress((void**)&hidH_p,  g_hidH);
    cudaGetSymbolAddress((void**)&attnH_p, g_attnH);
    cudaGetSymbolAddress((void**)&wqH_p,   g_wqH);
    cudaGetSymbolAddress((void**)&woH_p,   g_woH);
    cudaGetSymbolAddress((void**)&part_p,  g_part);

    cudaFuncSetAttribute(gemm_qkv, cudaFuncAttributeMaxDynamicSharedMemorySize, GEMM_SMEM);
    cudaFuncSetAttribute(gemm_wo,  cudaFuncAttributeMaxDynamicSharedMemorySize, GEMM_SMEM);
    cudaFuncSetAttribute(attn_mma, cudaFuncAttributeMaxDynamicSharedMemorySize, ATTN_SMEM);

    // 0) fused prologue: RoPE table + smem-staged operand images
    prologue<<<1856, 256>>>(hidden, wqkv, wo, pos);

    // 1) QKV = hidden @ Wqkv^T, fused RoPE epilogue -> g_qkvH fp16
    gemm_qkv<<<dim3(QKVD / 128, NTOK / 128), 256, GEMM_SMEM>>>(hidH_p, wqH_p, DD / 32);
    // 2) sliding-window attention (pre-roped fp16 inputs) -> g_attnH (A-image)
    attn_mma<<<dim3(SS / 128, BB * HH), 256, ATTN_SMEM>>>();
    // 3) Wo GEMM split-K x3 -> partials, then reduce into d_out
    gemm_wo<<<dim3(DD / 128, NTOK / 128, 3), 256, GEMM_SMEM>>>(attnH_p, woH_p, part_p,
                                                               DD, DD / 32);
    reduce3<<<NTOK * DD / 4 / 256, 256>>>(out);
}

// round 16
// speedup vs baseline: 1.0466x; 1.0466x over previous
#include <cuda_runtime.h>
#include <cuda_fp16.h>
#include <math.h>
#include <stdint.h>

// Problem constants
#define BB   2
#define SS   2048
#define DD   768
#define HH   12
#define HDIM 64
#define QKVD 2304           // 3*D per token
#define NTOK (BB*SS)        // 4096

// Scratch (allocation-free rule: __device__ globals)
__device__ __half g_qkvH[(size_t)NTOK * QKVD];  // roped Q(scaled),K + V, fp16 row-major
__device__ float  g_rope[(size_t)NTOK * 64];    // [token][cos32|sin32]
__device__ __half g_hidH[(size_t)NTOK * DD];    // hidden as A-image (fp16)
__device__ __half g_attnH[(size_t)NTOK * DD];   // attn out as A-image (fp16)
__device__ __half g_wqH[(size_t)QKVD * DD];     // Wqkv as B-image (fp16)
__device__ __half g_woH[(size_t)DD * DD];       // Wo as B-image (fp16)

__device__ __forceinline__ uint32_t smem_u32(const void* p) {
    uint32_t a;
    asm("{ .reg .u64 t; cvta.to.shared.u64 t, %1; cvt.u32.u64 %0, t; }"
        : "=r"(a) : "l"(p));
    return a;
}

__device__ __forceinline__ void mma_f16(float c[4], const uint32_t a[4], const uint32_t b[2]) {
    asm volatile(
        "mma.sync.aligned.m16n8k16.row.col.f32.f16.f16.f32 "
        "{%0,%1,%2,%3}, {%4,%5,%6,%7}, {%8,%9}, {%0,%1,%2,%3};"
        : "+f"(c[0]), "+f"(c[1]), "+f"(c[2]), "+f"(c[3])
        : "r"(a[0]), "r"(a[1]), "r"(a[2]), "r"(a[3]), "r"(b[0]), "r"(b[1]));
}

#define LDSM_X4(r0,r1,r2,r3,a) \
    asm volatile("ldmatrix.sync.aligned.m8n8.x4.shared.b16 {%0,%1,%2,%3}, [%4];" \
                 : "=r"(r0), "=r"(r1), "=r"(r2), "=r"(r3) : "r"(a))
#define LDSM_X4T(r0,r1,r2,r3,a) \
    asm volatile("ldmatrix.sync.aligned.m8n8.x4.trans.shared.b16 {%0,%1,%2,%3}, [%4];" \
                 : "=r"(r0), "=r"(r1), "=r"(r2), "=r"(r3) : "r"(a))

#define CP_ASYNC16(dst, src) \
    asm volatile("cp.async.cg.shared.global [%0], [%1], 16;" :: "r"(dst), "l"(src))
#define CP_COMMIT() asm volatile("cp.async.commit_group;" ::: "memory")
#define CP_WAIT4()  asm volatile("cp.async.wait_group 4;"  ::: "memory")

// ---------------------------------------------------------------------------
// fp16 tile-image local offsets (within one 128x32 tile = 4096 halves).
// ---------------------------------------------------------------------------
__device__ __forceinline__ int aimg_local(int r, int k) {
    const int mi = (r >> 4) & 7, rr = r & 15;
    const int ki = (k >> 4) & 1, kk = k & 15;
    const int lane = ((rr & 7) << 2) + ((kk & 7) >> 1);
    const int e = (kk & 1) + ((rr >> 3) << 1) + ((kk >> 3) << 2);
    return (((mi << 1) + ki) << 8) + (lane << 3) + e;
}
__device__ __forceinline__ int bimg_local(int n, int k) {
    const int pr = (n >> 4) & 7, p = (n >> 3) & 1, nn = n & 7;
    const int ki = (k >> 4) & 1, kk = k & 15;
    const int lane = (nn << 2) + ((kk & 7) >> 1);
    const int e = (kk & 1) + ((kk >> 3) << 1) + (p << 2);
    return (((pr << 1) + ki) << 8) + (lane << 3) + e;
}

// ---------------------------------------------------------------------------
// Fused prologue: RoPE table + smem-staged tile-image transforms.
// Blocks: [0,512) rope; [512,1280) hidden-A (768 tiles);
//         [1280,1712) Wqkv-B (432 tiles); [1712,1856) Wo-B (144 tiles).
// ---------------------------------------------------------------------------
__global__ void prologue(const float* __restrict__ hidden,
                         const float* __restrict__ wqkv,
                         const float* __restrict__ wo,
                         const int*   __restrict__ pos_ids)
{
    const int bid = blockIdx.x;
    const int t   = threadIdx.x;
    if (bid < 512) {
        const int idx = bid * 256 + t;                    // NTOK*32
        const int bs = idx >> 5;
        const int d  = idx & 31;
        const float FCOEF = -0.41524101186091903f;
        const float pos = (float)pos_ids[bs];
        const float f = pos * exp2f((float)d * FCOEF);
        float sn, cs;
        sincosf(f, &sn, &cs);
        g_rope[(size_t)bs * 64 + d]      = cs;
        g_rope[(size_t)bs * 64 + 32 + d] = sn;
        return;
    }

    __shared__ __half img[4096];
    const float* src;
    __half* dst;
    bool isA;
    if (bid < 1280) {
        const int tile = bid - 512;
        const int mt = tile / 24, kc = tile % 24;
        src = hidden + (size_t)mt * 128 * DD + kc * 32;
        dst = g_hidH + ((size_t)(mt * 24 + kc) << 12);
        isA = true;
    } else if (bid < 1712) {
        const int tile = bid - 1280;
        const int nt = tile / 24, kc = tile % 24;
        src = wqkv + (size_t)nt * 128 * DD + kc * 32;
        dst = g_wqH + ((size_t)(nt * 24 + kc) << 12);
        isA = false;
    } else {
        const int tile = bid - 1712;
        const int nt = tile / 24, kc = tile % 24;
        src = wo + (size_t)nt * 128 * DD + kc * 32;
        dst = g_woH + ((size_t)(nt * 24 + kc) << 12);
        isA = false;
    }

#pragma unroll
    for (int i = 0; i < 4; i++) {
        const int q = t + 256 * i;       // 0..1023
        const int r = q >> 3;            // row 0..127
        const int k = (q & 7) << 2;      // 0,4,..,28
        const float4 v = *(const float4*)(src + (size_t)r * DD + k);
        const int o0 = isA ? aimg_local(r, k)     : bimg_local(r, k);
        const int o1 = isA ? aimg_local(r, k + 2) : bimg_local(r, k + 2);
        *(__half2*)(img + o0) = __floats2half2_rn(v.x, v.y);
        *(__half2*)(img + o1) = __floats2half2_rn(v.z, v.w);
    }
    __syncthreads();
#pragma unroll
    for (int i = 0; i < 2; i++)
        ((uint4*)dst)[t + 256 * i] = ((const uint4*)img)[t + 256 * i];
}

// ---------------------------------------------------------------------------
// QKV GEMM with fused RoPE epilogue -> fp16 g_qkvH.
// CTA 128x128x32, 8 warps as 4m x 2n, warp tile 32x64 (head-aligned N).
// ---------------------------------------------------------------------------
#define GEMM_SMEM 98304   // 6 buffers x (8KB A + 8KB B)

__global__ __launch_bounds__(256, 2) void gemm_qkv(const __half* __restrict__ Aimg,
                                                   const __half* __restrict__ Bimg,
                                                   int ntileK)
{
    extern __shared__ __half smh[];
    const uint32_t sbase = smem_u32(smh);
    const int tid    = threadIdx.x;
    const int wid    = tid >> 5;
    const int lane   = tid & 31;
    const int mt     = blockIdx.y;
    const int nt     = blockIdx.x;
    const int warp_m = wid >> 1;   // 0..3
    const int warp_n = wid & 1;    // 0..1

    float acc[2][8][4];
#pragma unroll
    for (int a = 0; a < 2; a++)
#pragma unroll
        for (int b = 0; b < 8; b++)
#pragma unroll
            for (int r = 0; r < 4; r++) acc[a][b][r] = 0.f;

    const int nch = ntileK;
    const __half* Atile0 = Aimg + ((size_t)(mt * ntileK) << 12) + (tid << 3);
    const __half* Btile0 = Bimg + ((size_t)(nt * ntileK) << 12) + (tid << 3);

#define ISSUE(c) do {                                                     \
    if ((c) < nch) {                                                      \
        const __half* As_ = Atile0 + ((size_t)(c) << 12);                 \
        const __half* Bs_ = Btile0 + ((size_t)(c) << 12);                 \
        uint32_t sa_ = sbase + ((c) % 6) * 16384u + (tid << 4);           \
        CP_ASYNC16(sa_,          As_);                                    \
        CP_ASYNC16(sa_ + 4096u,  As_ + 2048);                             \
        CP_ASYNC16(sa_ + 8192u,  Bs_);                                    \
        CP_ASYNC16(sa_ + 12288u, Bs_ + 2048);                             \
    }                                                                     \
    CP_COMMIT();                                                          \
} while (0)

    ISSUE(0); ISSUE(1); ISSUE(2); ISSUE(3); ISSUE(4);

    const int afo = warp_m * 1024 + lane * 8;
    const int bfo = 4096 + warp_n * 2048 + lane * 8;

    for (int c = 0; c < nch; c++) {
        CP_WAIT4();
        __syncthreads();

        const __half* s = smh + (c % 6) * 8192;
#pragma unroll
        for (int ki = 0; ki < 2; ki++) {
            uint32_t af[2][4], bf[8][2];
#pragma unroll
            for (int a = 0; a < 2; a++) {
                uint4 v = *(const uint4*)(s + afo + a * 512 + ki * 256);
                af[a][0] = v.x; af[a][1] = v.y; af[a][2] = v.z; af[a][3] = v.w;
            }
#pragma unroll
            for (int t2 = 0; t2 < 4; t2++) {
                uint4 v = *(const uint4*)(s + bfo + t2 * 512 + ki * 256);
                bf[2*t2][0]   = v.x; bf[2*t2][1]   = v.y;
                bf[2*t2+1][0] = v.z; bf[2*t2+1][1] = v.w;
            }
#pragma unroll
            for (int a = 0; a < 2; a++)
#pragma unroll
                for (int b = 0; b < 8; b++)
                    mma_f16(acc[a][b], af[a], bf[b]);
        }
        ISSUE(c + 5);
    }

    const int g = lane >> 2, u = lane & 3;
    const int colb = nt * 128 + warp_n * 64;
    const int region = colb / DD;                // 0=Q, 1=K, 2=V
    const float SC = (region == 0) ? 0.18033688011112042f : 1.0f;

#pragma unroll
    for (int a = 0; a < 2; a++) {
        const int tok0 = mt * 128 + warp_m * 32 + a * 16 + g;
        const int tok1 = tok0 + 8;
        __half* o0 = g_qkvH + (size_t)tok0 * QKVD + colb;
        __half* o1 = g_qkvH + (size_t)tok1 * QKVD + colb;
        if (region == 2) {
#pragma unroll
            for (int b = 0; b < 8; b++) {
                const int cc = 8 * b + 2 * u;
                *(__half2*)(o0 + cc) = __floats2half2_rn(acc[a][b][0], acc[a][b][1]);
                *(__half2*)(o1 + cc) = __floats2half2_rn(acc[a][b][2], acc[a][b][3]);
            }
        } else {
            const float* rp0 = g_rope + (size_t)tok0 * 64;
            const float* rp1 = g_rope + (size_t)tok1 * 64;
#pragma unroll
            for (int b = 0; b < 4; b++) {
                const int d = 8 * b + 2 * u;
                const float x0 = acc[a][b][0],   x1 = acc[a][b][1];
                const float y0 = acc[a][b+4][0], y1 = acc[a][b+4][1];
                const float c0 = rp0[d], c1 = rp0[d+1], s0 = rp0[32+d], s1 = rp0[32+d+1];
                *(__half2*)(o0 + d)      = __floats2half2_rn((x0*c0 - y0*s0)*SC, (x1*c1 - y1*s1)*SC);
                *(__half2*)(o0 + 32 + d) = __floats2half2_rn((y0*c0 + x0*s0)*SC, (y1*c1 + x1*s1)*SC);
                const float x2 = acc[a][b][2],   x3 = acc[a][b][3];
                const float y2 = acc[a][b+4][2], y3 = acc[a][b+4][3];
                const float c2 = rp1[d], c3 = rp1[d+1], s2 = rp1[32+d], s3 = rp1[32+d+1];
                *(__half2*)(o1 + d)      = __floats2half2_rn((x2*c2 - y2*s2)*SC, (x3*c3 - y3*s3)*SC);
                *(__half2*)(o1 + 32 + d) = __floats2half2_rn((y2*c2 + x2*s2)*SC, (y3*c3 + x3*s3)*SC);
            }
        }
    }
#undef ISSUE
}

// ---------------------------------------------------------------------------
// fp16 GEMM on tile images (Wo; single-pass, writes d_out directly).
// ---------------------------------------------------------------------------
__global__ __launch_bounds__(256, 2) void gemm_h(const __half* __restrict__ Aimg,
                                                 const __half* __restrict__ Bimg,
                                                 float* __restrict__ C,
                                                 int N, int ntileK)
{
    extern __shared__ __half smh[];
    const uint32_t sbase = smem_u32(smh);
    const int tid    = threadIdx.x;
    const int wid    = tid >> 5;
    const int lane   = tid & 31;
    const int mt     = blockIdx.y;
    const int nt     = blockIdx.x;
    const int warp_m = wid >> 2;
    const int warp_n = wid & 3;

    float acc[4][4][4];
#pragma unroll
    for (int a = 0; a < 4; a++)
#pragma unroll
        for (int b = 0; b < 4; b++)
#pragma unroll
            for (int r = 0; r < 4; r++) acc[a][b][r] = 0.f;

    const int nch = ntileK;
    const __half* Atile0 = Aimg + ((size_t)(mt * ntileK) << 12) + (tid << 3);
    const __half* Btile0 = Bimg + ((size_t)(nt * ntileK) << 12) + (tid << 3);

#define ISSUE(c) do {                                                     \
    if ((c) < nch) {                                                      \
        const __half* As_ = Atile0 + ((size_t)(c) << 12);                 \
        const __half* Bs_ = Btile0 + ((size_t)(c) << 12);                 \
        uint32_t sa_ = sbase + ((c) % 6) * 16384u + (tid << 4);           \
        CP_ASYNC16(sa_,          As_);                                    \
        CP_ASYNC16(sa_ + 4096u,  As_ + 2048);                             \
        CP_ASYNC16(sa_ + 8192u,  Bs_);                                    \
        CP_ASYNC16(sa_ + 12288u, Bs_ + 2048);                             \
    }                                                                     \
    CP_COMMIT();                                                          \
} while (0)

    ISSUE(0); ISSUE(1); ISSUE(2); ISSUE(3); ISSUE(4);

    const int afo = warp_m * 2048 + lane * 8;
    const int bfo = 4096 + warp_n * 1024 + lane * 8;

    for (int c = 0; c < nch; c++) {
        CP_WAIT4();
        __syncthreads();

        const __half* s = smh + (c % 6) * 8192;
#pragma unroll
        for (int ki = 0; ki < 2; ki++) {
            uint32_t af[4][4], bf[4][2];
#pragma unroll
            for (int a = 0; a < 4; a++) {
                uint4 v = *(const uint4*)(s + afo + a * 512 + ki * 256);
                af[a][0] = v.x; af[a][1] = v.y; af[a][2] = v.z; af[a][3] = v.w;
            }
#pragma unroll
            for (int t2 = 0; t2 < 2; t2++) {
                uint4 v = *(const uint4*)(s + bfo + t2 * 512 + ki * 256);
                bf[2*t2][0]   = v.x; bf[2*t2][1]   = v.y;
                bf[2*t2+1][0] = v.z; bf[2*t2+1][1] = v.w;
            }
#pragma unroll
            for (int a = 0; a < 4; a++)
#pragma unroll
                for (int b = 0; b < 4; b++)
                    mma_f16(acc[a][b], af[a], bf[b]);
        }
        ISSUE(c + 5);
    }

    const int g = lane >> 2, u = lane & 3;
#pragma unroll
    for (int a = 0; a < 4; a++) {
        const int row = mt * 128 + warp_m * 64 + a * 16 + g;
#pragma unroll
        for (int b = 0; b < 4; b++) {
            const int col = nt * 128 + warp_n * 32 + b * 8 + 2 * u;
            *(float2*)(C + (size_t)row * N + col)       = make_float2(acc[a][b][0], acc[a][b][1]);
            *(float2*)(C + (size_t)(row + 8) * N + col) = make_float2(acc[a][b][2], acc[a][b][3]);
        }
    }
#undef ISSUE
}

// ---------------------------------------------------------------------------
// Sliding-window attention (unchanged).
// ---------------------------------------------------------------------------
#define KPH 72
#define VHP 72
#define QPH 72
#define VH_OFF (256 * KPH)
#define QH_OFF (VH_OFF + 256 * VHP)
#define ATTN_SMEM ((QH_OFF + 128 * QPH) * 2)   // 92160 bytes

__global__ __launch_bounds__(256, 2) void attn_mma()
{
    extern __shared__ __half smha[];
    __half* Kh = smha;
    __half* Vh = smha + VH_OFF;
    __half* Qh = smha + QH_OFF;

    const int tid  = threadIdx.x;
    const int lane = tid & 31;
    const int w    = tid >> 5;
    const int g    = lane >> 2;
    const int t    = lane & 3;
    const int j    = lane >> 3;
    const int rim  = lane & 7;
    const int qb   = blockIdx.x;
    const int bh   = blockIdx.y;
    const int b    = bh / HH;
    const int h    = bh % HH;
    const int kstart = qb * 128 - 64;

    // ---- Phase A: pure coalesced copy ----
    {
        const int rg8 = tid >> 3;
        const int c8  = tid & 7;
#pragma unroll
        for (int i = 0; i < 8; i++) {
            const int r  = rg8 + 32 * i;
            const int kg = kstart + r;
            uint4* kd = (uint4*)(Kh + r * KPH + c8 * 8);
            uint4* vd = (uint4*)(Vh + r * VHP + c8 * 8);
            if (kg >= 0 && kg < SS) {
                const __half* src = g_qkvH + ((size_t)(b * SS + kg)) * QKVD + h * HDIM + c8 * 8;
                *kd = *(const uint4*)(src + DD);
                *vd = *(const uint4*)(src + 2 * DD);
            } else {
                const uint4 z = make_uint4(0, 0, 0, 0);
                *kd = z;
                *vd = z;
            }
        }
#pragma unroll
        for (int i = 0; i < 4; i++) {
            const int r  = rg8 + 32 * i;
            const int qg = qb * 128 + r;
            *(uint4*)(Qh + r * QPH + c8 * 8) =
                *(const uint4*)(g_qkvH + ((size_t)(b * SS + qg)) * QKVD + h * HDIM + c8 * 8);
        }
    }
    __syncthreads();

    const uint32_t kh_base = smem_u32(Kh);
    const uint32_t vh_base = smem_u32(Vh);
    const uint32_t qh_base = smem_u32(Qh);
    const uint32_t pw_base = qh_base + (uint32_t)((w << 4) * QPH * 2);

    const int rl = (w << 4) + g;
    uint32_t aq[4][4];
    {
        const uint32_t qa = qh_base +
            (uint32_t)((((w << 4) + rim + 8 * (j & 1)) * QPH + 8 * (j >> 1)) * 2);
#pragma unroll
        for (int s = 0; s < 4; s++)
            LDSM_X4(aq[s][0], aq[s][1], aq[s][2], aq[s][3], qa + 32u * s);
    }
    __syncwarp();

    float m0 = -1e4f, m1 = -1e4f, l0 = 0.f, l1 = 0.f;
    float oacc[8][4];
#pragma unroll
    for (int d = 0; d < 8; d++)
#pragma unroll
        for (int r = 0; r < 4; r++) oacc[d][r] = 0.f;

    __half* Pw = Qh + (w << 4) * QPH;
    const int cw = (w >= 4) ? 1 : 0;

    const uint32_t k_lds0 = kh_base + (uint32_t)(((8 * (j >> 1) + rim) * KPH + 8 * (j & 1)) * 2);
    const uint32_t v_lds0 = vh_base + (uint32_t)(((8 * (j & 1) + rim) * VHP + 8 * (j >> 1)) * 2);
    const uint32_t p_lds0 = pw_base + (uint32_t)(((rim + 8 * (j & 1)) * QPH + 8 * (j >> 1)) * 2);

    for (int ci = 0; ci < 3; ci++) {
        const int kbase = (cw + ci) * 64;

        float sacc[8][4];
#pragma unroll
        for (int q = 0; q < 8; q++)
#pragma unroll
            for (int r = 0; r < 4; r++) sacc[q][r] = 0.f;

#pragma unroll
        for (int s = 0; s < 4; s++) {
#pragma unroll
            for (int jp = 0; jp < 4; jp++) {
                uint32_t r0, r1, r2, r3;
                const uint32_t ka = k_lds0 +
                    (uint32_t)((kbase + 16 * jp) * KPH * 2) + 32u * s;
                LDSM_X4(r0, r1, r2, r3, ka);
                uint32_t b0[2] = {r0, r1};
                uint32_t b1[2] = {r2, r3};
                mma_f16(sacc[2 * jp],     aq[s], b0);
                mma_f16(sacc[2 * jp + 1], aq[s], b1);
            }
        }

        float mx0 = -30000.f, mx1 = -30000.f;
#pragma unroll
        for (int jt = 0; jt < 8; jt++) {
            const int k0 = kbase + 8 * jt + 2 * t;
            const int k1 = k0 + 1;
            const int kg0 = kstart + k0, kg1 = kstart + k1;
            const bool in0 = (kg0 >= 0) & (kg0 < SS);
            const bool in1 = (kg1 >= 0) & (kg1 < SS);
            const bool v00 = in0 && ((unsigned)(k0 - rl) <= 128u);
            const bool v01 = in1 && ((unsigned)(k1 - rl) <= 128u);
            const bool v10 = in0 && ((unsigned)(k0 - rl - 8) <= 128u);
            const bool v11 = in1 && ((unsigned)(k1 - rl - 8) <= 128u);
            sacc[jt][0] = v00 ? sacc[jt][0] : -30000.f;
            sacc[jt][1] = v01 ? sacc[jt][1] : -30000.f;
            sacc[jt][2] = v10 ? sacc[jt][2] : -30000.f;
            sacc[jt][3] = v11 ? sacc[jt][3] : -30000.f;
            mx0 = fmaxf(mx0, fmaxf(sacc[jt][0], sacc[jt][1]));
            mx1 = fmaxf(mx1, fmaxf(sacc[jt][2], sacc[jt][3]));
        }
        mx0 = fmaxf(mx0, __shfl_xor_sync(0xffffffff, mx0, 1));
        mx0 = fmaxf(mx0, __shfl_xor_sync(0xffffffff, mx0, 2));
        mx1 = fmaxf(mx1, __shfl_xor_sync(0xffffffff, mx1, 1));
        mx1 = fmaxf(mx1, __shfl_xor_sync(0xffffffff, mx1, 2));

        const float m0n = fmaxf(m0, mx0);
        const float m1n = fmaxf(m1, mx1);
        const float a0 = exp2f(m0 - m0n);
        const float a1 = exp2f(m1 - m1n);
        m0 = m0n; m1 = m1n;
        l0 *= a0; l1 *= a1;
#pragma unroll
        for (int d = 0; d < 8; d++) {
            oacc[d][0] *= a0; oacc[d][1] *= a0;
            oacc[d][2] *= a1; oacc[d][3] *= a1;
        }

        float rs0 = 0.f, rs1 = 0.f;
#pragma unroll
        for (int jt = 0; jt < 8; jt++) {
            __half2 hp0 = __floats2half2_rn(exp2f(sacc[jt][0] - m0),
                                            exp2f(sacc[jt][1] - m0));
            __half2 hp1 = __floats2half2_rn(exp2f(sacc[jt][2] - m1),
                                            exp2f(sacc[jt][3] - m1));
            float2 f0 = __half22float2(hp0);
            float2 f1 = __half22float2(hp1);
            rs0 += f0.x + f0.y;
            rs1 += f1.x + f1.y;
            const int pc = 8 * jt + 2 * t;
            *(__half2*)(Pw + g * QPH + pc)       = hp0;
            *(__half2*)(Pw + (g + 8) * QPH + pc) = hp1;
        }
        rs0 += __shfl_xor_sync(0xffffffff, rs0, 1);
        rs0 += __shfl_xor_sync(0xffffffff, rs0, 2);
        rs1 += __shfl_xor_sync(0xffffffff, rs1, 1);
        rs1 += __shfl_xor_sync(0xffffffff, rs1, 2);
        l0 += rs0; l1 += rs1;
        __syncwarp();

#pragma unroll
        for (int s = 0; s < 4; s++) {
            uint32_t pa[4];
            LDSM_X4(pa[0], pa[1], pa[2], pa[3], p_lds0 + 32u * s);
#pragma unroll
            for (int dp = 0; dp < 4; dp++) {
                uint32_t r0, r1, r2, r3;
                const uint32_t va = v_lds0 +
                    (uint32_t)((kbase + 16 * s) * VHP * 2) + 32u * dp;
                LDSM_X4T(r0, r1, r2, r3, va);
                uint32_t b0[2] = {r0, r1};
                uint32_t b1[2] = {r2, r3};
                mma_f16(oacc[2 * dp],     pa, b0);
                mma_f16(oacc[2 * dp + 1], pa, b1);
            }
        }
        __syncwarp();
    }

    __syncthreads();
    __half* stage = Kh;
    const float inv0 = 1.f / l0;
    const float inv1 = 1.f / l1;
#pragma unroll
    for (int u = 0; u < 4; u++) {
        __half2 e01 = __floats2half2_rn(oacc[2*u][0]   * inv0, oacc[2*u][1]   * inv0);
        __half2 e23 = __floats2half2_rn(oacc[2*u][2]   * inv1, oacc[2*u][3]   * inv1);
        __half2 e45 = __floats2half2_rn(oacc[2*u+1][0] * inv0, oacc[2*u+1][1] * inv0);
        __half2 e67 = __floats2half2_rn(oacc[2*u+1][2] * inv1, oacc[2*u+1][3] * inv1);
        uint4 pack;
        pack.x = *(uint32_t*)&e01;
        pack.y = *(uint32_t*)&e23;
        pack.z = *(uint32_t*)&e45;
        pack.w = *(uint32_t*)&e67;
        __half* dst = stage + ((u >> 1) << 12) + (((w << 1) + (u & 1)) << 8) + (lane << 3);
        *(uint4*)dst = pack;
    }
    __syncthreads();

    {
        const int mt = (b * SS + qb * 128) >> 7;
        const int kc0 = h * 2;
        __half* gdst = g_attnH + ((size_t)(mt * (DD / 32) + kc0) << 12);
        const uint4* src = (const uint4*)stage;
        uint4* dst = (uint4*)gdst;
#pragma unroll
        for (int i = 0; i < 4; i++)
            dst[tid + 256 * i] = src[tid + 256 * i];
    }
}

// ---------------------------------------------------------------------------
extern "C" void kernel_launch(void* const* d_in, const int* in_sizes, int n_in,
                              void* d_out, int out_size)
{
    const float* hidden = (const float*)d_in[0];
    const float* wqkv   = (const float*)d_in[1];
    const float* wo     = (const float*)d_in[2];
    const int*   pos    = (const int*)d_in[4];
    float*       out    = (float*)d_out;

    __half *hidH_p, *attnH_p, *wqH_p, *woH_p;
    cudaGetSymbolAddress((void**)&hidH_p,  g_hidH);
    cudaGetSymbolAddress((void**)&attnH_p, g_attnH);
    cudaGetSymbolAddress((void**)&wqH_p,   g_wqH);
    cudaGetSymbolAddress((void**)&woH_p,   g_woH);

    cudaFuncSetAttribute(gemm_qkv, cudaFuncAttributeMaxDynamicSharedMemorySize, GEMM_SMEM);
    cudaFuncSetAttribute(gemm_h,   cudaFuncAttributeMaxDynamicSharedMemorySize, GEMM_SMEM);
    cudaFuncSetAttribute(attn_mma, cudaFuncAttributeMaxDynamicSharedMemorySize, ATTN_SMEM);

    // 0) fused prologue: RoPE table + smem-staged operand images
    prologue<<<1856, 256>>>(hidden, wqkv, wo, pos);

    // 1) QKV = hidden @ Wqkv^T, fused RoPE epilogue -> g_qkvH fp16
    gemm_qkv<<<dim3(QKVD / 128, NTOK / 128), 256, GEMM_SMEM>>>(hidH_p, wqH_p, DD / 32);
    // 2) sliding-window attention (pre-roped fp16 inputs) -> g_attnH (A-image)
    attn_mma<<<dim3(SS / 128, BB * HH), 256, ATTN_SMEM>>>();
    // 3) out = attn @ Wo^T (single pass, direct to d_out)
    gemm_h<<<dim3(DD / 128, NTOK / 128), 256, GEMM_SMEM>>>(attnH_p, woH_p, out,
                                                           DD, DD / 32);
}

// round 17
// speedup vs baseline: 1.0950x; 1.0462x over previous
#include <cuda_runtime.h>
#include <cuda_fp16.h>
#include <math.h>
#include <stdint.h>

// Problem constants
#define BB   2
#define SS   2048
#define DD   768
#define HH   12
#define HDIM 64
#define QKVD 2304           // 3*D per token
#define NTOK (BB*SS)        // 4096

// Scratch (allocation-free rule: __device__ globals)
__device__ __half g_qkvH[(size_t)NTOK * QKVD];  // roped Q(scaled),K + V, fp16 row-major
__device__ float  g_rope[(size_t)NTOK * 64];    // [token][cos32|sin32]
__device__ __half g_hidH[(size_t)NTOK * DD];    // hidden as A-image (fp16)
__device__ __half g_attnH[(size_t)NTOK * DD];   // attn out as A-image (fp16)
__device__ __half g_wqH[(size_t)QKVD * DD];     // Wqkv as B-image (fp16)
__device__ __half g_woH[(size_t)DD * DD];       // Wo as B-image (fp16)

__device__ __forceinline__ uint32_t smem_u32(const void* p) {
    uint32_t a;
    asm("{ .reg .u64 t; cvta.to.shared.u64 t, %1; cvt.u32.u64 %0, t; }"
        : "=r"(a) : "l"(p));
    return a;
}

__device__ __forceinline__ void mma_f16(float c[4], const uint32_t a[4], const uint32_t b[2]) {
    asm volatile(
        "mma.sync.aligned.m16n8k16.row.col.f32.f16.f16.f32 "
        "{%0,%1,%2,%3}, {%4,%5,%6,%7}, {%8,%9}, {%0,%1,%2,%3};"
        : "+f"(c[0]), "+f"(c[1]), "+f"(c[2]), "+f"(c[3])
        : "r"(a[0]), "r"(a[1]), "r"(a[2]), "r"(a[3]), "r"(b[0]), "r"(b[1]));
}

#define LDSM_X4(r0,r1,r2,r3,a) \
    asm volatile("ldmatrix.sync.aligned.m8n8.x4.shared.b16 {%0,%1,%2,%3}, [%4];" \
                 : "=r"(r0), "=r"(r1), "=r"(r2), "=r"(r3) : "r"(a))
#define LDSM_X4T(r0,r1,r2,r3,a) \
    asm volatile("ldmatrix.sync.aligned.m8n8.x4.trans.shared.b16 {%0,%1,%2,%3}, [%4];" \
                 : "=r"(r0), "=r"(r1), "=r"(r2), "=r"(r3) : "r"(a))

#define CP_ASYNC16(dst, src) \
    asm volatile("cp.async.cg.shared.global [%0], [%1], 16;" :: "r"(dst), "l"(src))
#define CP_COMMIT() asm volatile("cp.async.commit_group;" ::: "memory")
#define CP_WAIT4()  asm volatile("cp.async.wait_group 4;"  ::: "memory")

// ---------------------------------------------------------------------------
// fp16 tile-image local offsets (within one 128x32 tile = 4096 halves).
// ---------------------------------------------------------------------------
__device__ __forceinline__ int aimg_local(int r, int k) {
    const int mi = (r >> 4) & 7, rr = r & 15;
    const int ki = (k >> 4) & 1, kk = k & 15;
    const int lane = ((rr & 7) << 2) + ((kk & 7) >> 1);
    const int e = (kk & 1) + ((rr >> 3) << 1) + ((kk >> 3) << 2);
    return (((mi << 1) + ki) << 8) + (lane << 3) + e;
}
__device__ __forceinline__ int bimg_local(int n, int k) {
    const int pr = (n >> 4) & 7, p = (n >> 3) & 1, nn = n & 7;
    const int ki = (k >> 4) & 1, kk = k & 15;
    const int lane = (nn << 2) + ((kk & 7) >> 1);
    const int e = (kk & 1) + ((kk >> 3) << 1) + (p << 2);
    return (((pr << 1) + ki) << 8) + (lane << 3) + e;
}

// ---------------------------------------------------------------------------
// Fused prologue: RoPE table + smem-staged tile-image transforms.
// ---------------------------------------------------------------------------
__global__ void prologue(const float* __restrict__ hidden,
                         const float* __restrict__ wqkv,
                         const float* __restrict__ wo,
                         const int*   __restrict__ pos_ids)
{
    const int bid = blockIdx.x;
    const int t   = threadIdx.x;
    if (bid < 512) {
        const int idx = bid * 256 + t;                    // NTOK*32
        const int bs = idx >> 5;
        const int d  = idx & 31;
        const float FCOEF = -0.41524101186091903f;
        const float pos = (float)pos_ids[bs];
        const float f = pos * exp2f((float)d * FCOEF);
        float sn, cs;
        sincosf(f, &sn, &cs);
        g_rope[(size_t)bs * 64 + d]      = cs;
        g_rope[(size_t)bs * 64 + 32 + d] = sn;
        return;
    }

    __shared__ __half img[4096];
    const float* src;
    __half* dst;
    bool isA;
    if (bid < 1280) {
        const int tile = bid - 512;
        const int mt = tile / 24, kc = tile % 24;
        src = hidden + (size_t)mt * 128 * DD + kc * 32;
        dst = g_hidH + ((size_t)(mt * 24 + kc) << 12);
        isA = true;
    } else if (bid < 1712) {
        const int tile = bid - 1280;
        const int nt = tile / 24, kc = tile % 24;
        src = wqkv + (size_t)nt * 128 * DD + kc * 32;
        dst = g_wqH + ((size_t)(nt * 24 + kc) << 12);
        isA = false;
    } else {
        const int tile = bid - 1712;
        const int nt = tile / 24, kc = tile % 24;
        src = wo + (size_t)nt * 128 * DD + kc * 32;
        dst = g_woH + ((size_t)(nt * 24 + kc) << 12);
        isA = false;
    }

#pragma unroll
    for (int i = 0; i < 4; i++) {
        const int q = t + 256 * i;
        const int r = q >> 3;
        const int k = (q & 7) << 2;
        const float4 v = *(const float4*)(src + (size_t)r * DD + k);
        const int o0 = isA ? aimg_local(r, k)     : bimg_local(r, k);
        const int o1 = isA ? aimg_local(r, k + 2) : bimg_local(r, k + 2);
        *(__half2*)(img + o0) = __floats2half2_rn(v.x, v.y);
        *(__half2*)(img + o1) = __floats2half2_rn(v.z, v.w);
    }
    __syncthreads();
#pragma unroll
    for (int i = 0; i < 2; i++)
        ((uint4*)dst)[t + 256 * i] = ((const uint4*)img)[t + 256 * i];
}

// ---------------------------------------------------------------------------
// QKV GEMM with fused RoPE epilogue -> fp16 g_qkvH (unchanged).
// ---------------------------------------------------------------------------
#define GEMM_SMEM 98304   // 6 buffers x (8KB A + 8KB B)

__global__ __launch_bounds__(256, 2) void gemm_qkv(const __half* __restrict__ Aimg,
                                                   const __half* __restrict__ Bimg,
                                                   int ntileK)
{
    extern __shared__ __half smh[];
    const uint32_t sbase = smem_u32(smh);
    const int tid    = threadIdx.x;
    const int wid    = tid >> 5;
    const int lane   = tid & 31;
    const int mt     = blockIdx.y;
    const int nt     = blockIdx.x;
    const int warp_m = wid >> 1;
    const int warp_n = wid & 1;

    float acc[2][8][4];
#pragma unroll
    for (int a = 0; a < 2; a++)
#pragma unroll
        for (int b = 0; b < 8; b++)
#pragma unroll
            for (int r = 0; r < 4; r++) acc[a][b][r] = 0.f;

    const int nch = ntileK;
    const __half* Atile0 = Aimg + ((size_t)(mt * ntileK) << 12) + (tid << 3);
    const __half* Btile0 = Bimg + ((size_t)(nt * ntileK) << 12) + (tid << 3);

#define ISSUE(c) do {                                                     \
    if ((c) < nch) {                                                      \
        const __half* As_ = Atile0 + ((size_t)(c) << 12);                 \
        const __half* Bs_ = Btile0 + ((size_t)(c) << 12);                 \
        uint32_t sa_ = sbase + ((c) % 6) * 16384u + (tid << 4);           \
        CP_ASYNC16(sa_,          As_);                                    \
        CP_ASYNC16(sa_ + 4096u,  As_ + 2048);                             \
        CP_ASYNC16(sa_ + 8192u,  Bs_);                                    \
        CP_ASYNC16(sa_ + 12288u, Bs_ + 2048);                             \
    }                                                                     \
    CP_COMMIT();                                                          \
} while (0)

    ISSUE(0); ISSUE(1); ISSUE(2); ISSUE(3); ISSUE(4);

    const int afo = warp_m * 1024 + lane * 8;
    const int bfo = 4096 + warp_n * 2048 + lane * 8;

    for (int c = 0; c < nch; c++) {
        CP_WAIT4();
        __syncthreads();

        const __half* s = smh + (c % 6) * 8192;
#pragma unroll
        for (int ki = 0; ki < 2; ki++) {
            uint32_t af[2][4], bf[8][2];
#pragma unroll
            for (int a = 0; a < 2; a++) {
                uint4 v = *(const uint4*)(s + afo + a * 512 + ki * 256);
                af[a][0] = v.x; af[a][1] = v.y; af[a][2] = v.z; af[a][3] = v.w;
            }
#pragma unroll
            for (int t2 = 0; t2 < 4; t2++) {
                uint4 v = *(const uint4*)(s + bfo + t2 * 512 + ki * 256);
                bf[2*t2][0]   = v.x; bf[2*t2][1]   = v.y;
                bf[2*t2+1][0] = v.z; bf[2*t2+1][1] = v.w;
            }
#pragma unroll
            for (int a = 0; a < 2; a++)
#pragma unroll
                for (int b = 0; b < 8; b++)
                    mma_f16(acc[a][b], af[a], bf[b]);
        }
        ISSUE(c + 5);
    }

    const int g = lane >> 2, u = lane & 3;
    const int colb = nt * 128 + warp_n * 64;
    const int region = colb / DD;
    const float SC = (region == 0) ? 0.18033688011112042f : 1.0f;

#pragma unroll
    for (int a = 0; a < 2; a++) {
        const int tok0 = mt * 128 + warp_m * 32 + a * 16 + g;
        const int tok1 = tok0 + 8;
        __half* o0 = g_qkvH + (size_t)tok0 * QKVD + colb;
        __half* o1 = g_qkvH + (size_t)tok1 * QKVD + colb;
        if (region == 2) {
#pragma unroll
            for (int b = 0; b < 8; b++) {
                const int cc = 8 * b + 2 * u;
                *(__half2*)(o0 + cc) = __floats2half2_rn(acc[a][b][0], acc[a][b][1]);
                *(__half2*)(o1 + cc) = __floats2half2_rn(acc[a][b][2], acc[a][b][3]);
            }
        } else {
            const float* rp0 = g_rope + (size_t)tok0 * 64;
            const float* rp1 = g_rope + (size_t)tok1 * 64;
#pragma unroll
            for (int b = 0; b < 4; b++) {
                const int d = 8 * b + 2 * u;
                const float x0 = acc[a][b][0],   x1 = acc[a][b][1];
                const float y0 = acc[a][b+4][0], y1 = acc[a][b+4][1];
                const float c0 = rp0[d], c1 = rp0[d+1], s0 = rp0[32+d], s1 = rp0[32+d+1];
                *(__half2*)(o0 + d)      = __floats2half2_rn((x0*c0 - y0*s0)*SC, (x1*c1 - y1*s1)*SC);
                *(__half2*)(o0 + 32 + d) = __floats2half2_rn((y0*c0 + x0*s0)*SC, (y1*c1 + x1*s1)*SC);
                const float x2 = acc[a][b][2],   x3 = acc[a][b][3];
                const float y2 = acc[a][b+4][2], y3 = acc[a][b+4][3];
                const float c2 = rp1[d], c3 = rp1[d+1], s2 = rp1[32+d], s3 = rp1[32+d+1];
                *(__half2*)(o1 + d)      = __floats2half2_rn((x2*c2 - y2*s2)*SC, (x3*c3 - y3*s3)*SC);
                *(__half2*)(o1 + 32 + d) = __floats2half2_rn((y2*c2 + x2*s2)*SC, (y3*c3 + x3*s3)*SC);
            }
        }
    }
#undef ISSUE
}

// ---------------------------------------------------------------------------
// Wo GEMM: CTA 128x64x32, 8 warps (4m x 2n), warp tile 32x32.
// 6-stage ring (12KB/stage = 72KB), 3 CTAs/SM, grid (12, 32) = 384.
// ---------------------------------------------------------------------------
#define WO_SMEM 73728   // 6 x (8KB A + 4KB B)

__global__ __launch_bounds__(256, 3) void gemm_wo(const __half* __restrict__ Aimg,
                                                  const __half* __restrict__ Bimg,
                                                  float* __restrict__ C,
                                                  int N, int ntileK)
{
    extern __shared__ __half smh[];
    const uint32_t sbase = smem_u32(smh);
    const int tid    = threadIdx.x;
    const int wid    = tid >> 5;
    const int lane   = tid & 31;
    const int mt     = blockIdx.y;
    const int nt2    = blockIdx.x;     // 64-col tile index 0..11
    const int warp_m = wid >> 1;       // 0..3
    const int warp_n = wid & 1;        // 0..1

    float acc[2][4][4];
#pragma unroll
    for (int a = 0; a < 2; a++)
#pragma unroll
        for (int b = 0; b < 4; b++)
#pragma unroll
            for (int r = 0; r < 4; r++) acc[a][b][r] = 0.f;

    const int nch = ntileK;
    const __half* Atile0 = Aimg + ((size_t)(mt * ntileK) << 12) + (tid << 3);
    const __half* Btile0 = Bimg + ((size_t)((nt2 >> 1) * ntileK) << 12)
                                + ((nt2 & 1) << 11) + (tid << 3);

#define ISSUE(c) do {                                                     \
    if ((c) < nch) {                                                      \
        const __half* As_ = Atile0 + ((size_t)(c) << 12);                 \
        const __half* Bs_ = Btile0 + ((size_t)(c) << 12);                 \
        uint32_t sa_ = sbase + ((c) % 6) * 12288u + (tid << 4);           \
        CP_ASYNC16(sa_,          As_);                                    \
        CP_ASYNC16(sa_ + 4096u,  As_ + 2048);                             \
        CP_ASYNC16(sa_ + 8192u,  Bs_);                                    \
    }                                                                     \
    CP_COMMIT();                                                          \
} while (0)

    ISSUE(0); ISSUE(1); ISSUE(2); ISSUE(3); ISSUE(4);

    const int afo = warp_m * 1024 + lane * 8;          // + a*512 + ki*256
    const int bfo = 4096 + warp_n * 1024 + lane * 8;   // + t2*512 + ki*256

    for (int c = 0; c < nch; c++) {
        CP_WAIT4();
        __syncthreads();

        const __half* s = smh + (c % 6) * 6144;        // 6144 halves per stage
#pragma unroll
        for (int ki = 0; ki < 2; ki++) {
            uint32_t af[2][4], bf[4][2];
#pragma unroll
            for (int a = 0; a < 2; a++) {
                uint4 v = *(const uint4*)(s + afo + a * 512 + ki * 256);
                af[a][0] = v.x; af[a][1] = v.y; af[a][2] = v.z; af[a][3] = v.w;
            }
#pragma unroll
            for (int t2 = 0; t2 < 2; t2++) {
                uint4 v = *(const uint4*)(s + bfo + t2 * 512 + ki * 256);
                bf[2*t2][0]   = v.x; bf[2*t2][1]   = v.y;
                bf[2*t2+1][0] = v.z; bf[2*t2+1][1] = v.w;
            }
#pragma unroll
            for (int a = 0; a < 2; a++)
#pragma unroll
                for (int b = 0; b < 4; b++)
                    mma_f16(acc[a][b], af[a], bf[b]);
        }
        ISSUE(c + 5);
    }

    const int g = lane >> 2, u = lane & 3;
#pragma unroll
    for (int a = 0; a < 2; a++) {
        const int row = mt * 128 + warp_m * 32 + a * 16 + g;
#pragma unroll
        for (int b = 0; b < 4; b++) {
            const int col = nt2 * 64 + warp_n * 32 + b * 8 + 2 * u;
            *(float2*)(C + (size_t)row * N + col)       = make_float2(acc[a][b][0], acc[a][b][1]);
            *(float2*)(C + (size_t)(row + 8) * N + col) = make_float2(acc[a][b][2], acc[a][b][3]);
        }
    }
#undef ISSUE
}

// ---------------------------------------------------------------------------
// Sliding-window attention (unchanged).
// ---------------------------------------------------------------------------
#define KPH 72
#define VHP 72
#define QPH 72
#define VH_OFF (256 * KPH)
#define QH_OFF (VH_OFF + 256 * VHP)
#define ATTN_SMEM ((QH_OFF + 128 * QPH) * 2)   // 92160 bytes

__global__ __launch_bounds__(256, 2) void attn_mma()
{
    extern __shared__ __half smha[];
    __half* Kh = smha;
    __half* Vh = smha + VH_OFF;
    __half* Qh = smha + QH_OFF;

    const int tid  = threadIdx.x;
    const int lane = tid & 31;
    const int w    = tid >> 5;
    const int g    = lane >> 2;
    const int t    = lane & 3;
    const int j    = lane >> 3;
    const int rim  = lane & 7;
    const int qb   = blockIdx.x;
    const int bh   = blockIdx.y;
    const int b    = bh / HH;
    const int h    = bh % HH;
    const int kstart = qb * 128 - 64;

    // ---- Phase A: pure coalesced copy ----
    {
        const int rg8 = tid >> 3;
        const int c8  = tid & 7;
#pragma unroll
        for (int i = 0; i < 8; i++) {
            const int r  = rg8 + 32 * i;
            const int kg = kstart + r;
            uint4* kd = (uint4*)(Kh + r * KPH + c8 * 8);
            uint4* vd = (uint4*)(Vh + r * VHP + c8 * 8);
            if (kg >= 0 && kg < SS) {
                const __half* src = g_qkvH + ((size_t)(b * SS + kg)) * QKVD + h * HDIM + c8 * 8;
                *kd = *(const uint4*)(src + DD);
                *vd = *(const uint4*)(src + 2 * DD);
            } else {
                const uint4 z = make_uint4(0, 0, 0, 0);
                *kd = z;
                *vd = z;
            }
        }
#pragma unroll
        for (int i = 0; i < 4; i++) {
            const int r  = rg8 + 32 * i;
            const int qg = qb * 128 + r;
            *(uint4*)(Qh + r * QPH + c8 * 8) =
                *(const uint4*)(g_qkvH + ((size_t)(b * SS + qg)) * QKVD + h * HDIM + c8 * 8);
        }
    }
    __syncthreads();

    const uint32_t kh_base = smem_u32(Kh);
    const uint32_t vh_base = smem_u32(Vh);
    const uint32_t qh_base = smem_u32(Qh);
    const uint32_t pw_base = qh_base + (uint32_t)((w << 4) * QPH * 2);

    const int rl = (w << 4) + g;
    uint32_t aq[4][4];
    {
        const uint32_t qa = qh_base +
            (uint32_t)((((w << 4) + rim + 8 * (j & 1)) * QPH + 8 * (j >> 1)) * 2);
#pragma unroll
        for (int s = 0; s < 4; s++)
            LDSM_X4(aq[s][0], aq[s][1], aq[s][2], aq[s][3], qa + 32u * s);
    }
    __syncwarp();

    float m0 = -1e4f, m1 = -1e4f, l0 = 0.f, l1 = 0.f;
    float oacc[8][4];
#pragma unroll
    for (int d = 0; d < 8; d++)
#pragma unroll
        for (int r = 0; r < 4; r++) oacc[d][r] = 0.f;

    __half* Pw = Qh + (w << 4) * QPH;
    const int cw = (w >= 4) ? 1 : 0;

    const uint32_t k_lds0 = kh_base + (uint32_t)(((8 * (j >> 1) + rim) * KPH + 8 * (j & 1)) * 2);
    const uint32_t v_lds0 = vh_base + (uint32_t)(((8 * (j & 1) + rim) * VHP + 8 * (j >> 1)) * 2);
    const uint32_t p_lds0 = pw_base + (uint32_t)(((rim + 8 * (j & 1)) * QPH + 8 * (j >> 1)) * 2);

    for (int ci = 0; ci < 3; ci++) {
        const int kbase = (cw + ci) * 64;

        float sacc[8][4];
#pragma unroll
        for (int q = 0; q < 8; q++)
#pragma unroll
            for (int r = 0; r < 4; r++) sacc[q][r] = 0.f;

#pragma unroll
        for (int s = 0; s < 4; s++) {
#pragma unroll
            for (int jp = 0; jp < 4; jp++) {
                uint32_t r0, r1, r2, r3;
                const uint32_t ka = k_lds0 +
                    (uint32_t)((kbase + 16 * jp) * KPH * 2) + 32u * s;
                LDSM_X4(r0, r1, r2, r3, ka);
                uint32_t b0[2] = {r0, r1};
                uint32_t b1[2] = {r2, r3};
                mma_f16(sacc[2 * jp],     aq[s], b0);
                mma_f16(sacc[2 * jp + 1], aq[s], b1);
            }
        }

        float mx0 = -30000.f, mx1 = -30000.f;
#pragma unroll
        for (int jt = 0; jt < 8; jt++) {
            const int k0 = kbase + 8 * jt + 2 * t;
            const int k1 = k0 + 1;
            const int kg0 = kstart + k0, kg1 = kstart + k1;
            const bool in0 = (kg0 >= 0) & (kg0 < SS);
            const bool in1 = (kg1 >= 0) & (kg1 < SS);
            const bool v00 = in0 && ((unsigned)(k0 - rl) <= 128u);
            const bool v01 = in1 && ((unsigned)(k1 - rl) <= 128u);
            const bool v10 = in0 && ((unsigned)(k0 - rl - 8) <= 128u);
            const bool v11 = in1 && ((unsigned)(k1 - rl - 8) <= 128u);
            sacc[jt][0] = v00 ? sacc[jt][0] : -30000.f;
            sacc[jt][1] = v01 ? sacc[jt][1] : -30000.f;
            sacc[jt][2] = v10 ? sacc[jt][2] : -30000.f;
            sacc[jt][3] = v11 ? sacc[jt][3] : -30000.f;
            mx0 = fmaxf(mx0, fmaxf(sacc[jt][0], sacc[jt][1]));
            mx1 = fmaxf(mx1, fmaxf(sacc[jt][2], sacc[jt][3]));
        }
        mx0 = fmaxf(mx0, __shfl_xor_sync(0xffffffff, mx0, 1));
        mx0 = fmaxf(mx0, __shfl_xor_sync(0xffffffff, mx0, 2));
        mx1 = fmaxf(mx1, __shfl_xor_sync(0xffffffff, mx1, 1));
        mx1 = fmaxf(mx1, __shfl_xor_sync(0xffffffff, mx1, 2));

        const float m0n = fmaxf(m0, mx0);
        const float m1n = fmaxf(m1, mx1);
        const float a0 = exp2f(m0 - m0n);
        const float a1 = exp2f(m1 - m1n);
        m0 = m0n; m1 = m1n;
        l0 *= a0; l1 *= a1;
#pragma unroll
        for (int d = 0; d < 8; d++) {
            oacc[d][0] *= a0; oacc[d][1] *= a0;
            oacc[d][2] *= a1; oacc[d][3] *= a1;
        }

        float rs0 = 0.f, rs1 = 0.f;
#pragma unroll
        for (int jt = 0; jt < 8; jt++) {
            __half2 hp0 = __floats2half2_rn(exp2f(sacc[jt][0] - m0),
                                            exp2f(sacc[jt][1] - m0));
            __half2 hp1 = __floats2half2_rn(exp2f(sacc[jt][2] - m1),
                                            exp2f(sacc[jt][3] - m1));
            float2 f0 = __half22float2(hp0);
            float2 f1 = __half22float2(hp1);
            rs0 += f0.x + f0.y;
            rs1 += f1.x + f1.y;
            const int pc = 8 * jt + 2 * t;
            *(__half2*)(Pw + g * QPH + pc)       = hp0;
            *(__half2*)(Pw + (g + 8) * QPH + pc) = hp1;
        }
        rs0 += __shfl_xor_sync(0xffffffff, rs0, 1);
        rs0 += __shfl_xor_sync(0xffffffff, rs0, 2);
        rs1 += __shfl_xor_sync(0xffffffff, rs1, 1);
        rs1 += __shfl_xor_sync(0xffffffff, rs1, 2);
        l0 += rs0; l1 += rs1;
        __syncwarp();

#pragma unroll
        for (int s = 0; s < 4; s++) {
            uint32_t pa[4];
            LDSM_X4(pa[0], pa[1], pa[2], pa[3], p_lds0 + 32u * s);
#pragma unroll
            for (int dp = 0; dp < 4; dp++) {
                uint32_t r0, r1, r2, r3;
                const uint32_t va = v_lds0 +
                    (uint32_t)((kbase + 16 * s) * VHP * 2) + 32u * dp;
                LDSM_X4T(r0, r1, r2, r3, va);
                uint32_t b0[2] = {r0, r1};
                uint32_t b1[2] = {r2, r3};
                mma_f16(oacc[2 * dp],     pa, b0);
                mma_f16(oacc[2 * dp + 1], pa, b1);
            }
        }
        __syncwarp();
    }

    __syncthreads();
    __half* stage = Kh;
    const float inv0 = 1.f / l0;
    const float inv1 = 1.f / l1;
#pragma unroll
    for (int u = 0; u < 4; u++) {
        __half2 e01 = __floats2half2_rn(oacc[2*u][0]   * inv0, oacc[2*u][1]   * inv0);
        __half2 e23 = __floats2half2_rn(oacc[2*u][2]   * inv1, oacc[2*u][3]   * inv1);
        __half2 e45 = __floats2half2_rn(oacc[2*u+1][0] * inv0, oacc[2*u+1][1] * inv0);
        __half2 e67 = __floats2half2_rn(oacc[2*u+1][2] * inv1, oacc[2*u+1][3] * inv1);
        uint4 pack;
        pack.x = *(uint32_t*)&e01;
        pack.y = *(uint32_t*)&e23;
        pack.z = *(uint32_t*)&e45;
        pack.w = *(uint32_t*)&e67;
        __half* dst = stage + ((u >> 1) << 12) + (((w << 1) + (u & 1)) << 8) + (lane << 3);
        *(uint4*)dst = pack;
    }
    __syncthreads();

    {
        const int mt = (b * SS + qb * 128) >> 7;
        const int kc0 = h * 2;
        __half* gdst = g_attnH + ((size_t)(mt * (DD / 32) + kc0) << 12);
        const uint4* src = (const uint4*)stage;
        uint4* dst = (uint4*)gdst;
#pragma unroll
        for (int i = 0; i < 4; i++)
            dst[tid + 256 * i] = src[tid + 256 * i];
    }
}

// ---------------------------------------------------------------------------
extern "C" void kernel_launch(void* const* d_in, const int* in_sizes, int n_in,
                              void* d_out, int out_size)
{
    const float* hidden = (const float*)d_in[0];
    const float* wqkv   = (const float*)d_in[1];
    const float* wo     = (const float*)d_in[2];
    const int*   pos    = (const int*)d_in[4];
    float*       out    = (float*)d_out;

    __half *hidH_p, *attnH_p, *wqH_p, *woH_p;
    cudaGetSymbolAddress((void**)&hidH_p,  g_hidH);
    cudaGetSymbolAddress((void**)&attnH_p, g_attnH);
    cudaGetSymbolAddress((void**)&wqH_p,   g_wqH);
    cudaGetSymbolAddress((void**)&woH_p,   g_woH);

    cudaFuncSetAttribute(gemm_qkv, cudaFuncAttributeMaxDynamicSharedMemorySize, GEMM_SMEM);
    cudaFuncSetAttribute(gemm_wo,  cudaFuncAttributeMaxDynamicSharedMemorySize, WO_SMEM);
    cudaFuncSetAttribute(attn_mma, cudaFuncAttributeMaxDynamicSharedMemorySize, ATTN_SMEM);

    // 0) fused prologue: RoPE table + smem-staged operand images
    prologue<<<1856, 256>>>(hidden, wqkv, wo, pos);

    // 1) QKV = hidden @ Wqkv^T, fused RoPE epilogue -> g_qkvH fp16
    gemm_qkv<<<dim3(QKVD / 128, NTOK / 128), 256, GEMM_SMEM>>>(hidH_p, wqH_p, DD / 32);
    // 2) sliding-window attention (pre-roped fp16 inputs) -> g_attnH (A-image)
    attn_mma<<<dim3(SS / 128, BB * HH), 256, ATTN_SMEM>>>();
    // 3) out = attn @ Wo^T, CTA 128x64, 3 CTAs/SM, grid 384
    gemm_wo<<<dim3(DD / 64, NTOK / 128), 256, WO_SMEM>>>(attnH_p, woH_p, out,
                                                         DD, DD / 32);
}